// round 2
// baseline (speedup 1.0000x reference)
#include <cuda_runtime.h>
#include <cuda_bf16.h>
#include <cstdint>

// Problem constants
#define BB    2
#define HW    4096
#define NTGT  4096
#define CC    512
#define HH    8
#define KNN   32
#define DH    64
#define MROWS (BB * HW)      // 8192 (also B*NTGT)
#define SCALE 0.125f         // DH^-0.5

// ---------------- scratch (device globals: allocation-free) ----------------
__device__ float g_q[(size_t)MROWS * CC];
__device__ float g_k[(size_t)MROWS * CC];
__device__ float g_v[(size_t)MROWS * CC];
__device__ float g_att[(size_t)MROWS * CC];

// ---------------- fp32 tiled GEMM:  C[M,N] = A[M,K] @ W[K,N] + bias --------
#define BM 128
#define BN 128
#define BK 16

__global__ void __launch_bounds__(256, 2) sgemm_bias(
    const float* __restrict__ A, const float* __restrict__ W,
    const float* __restrict__ bias, float* __restrict__ C,
    int M, int N, int K)
{
    __shared__ __align__(16) float As[2][BK][BM];
    __shared__ __align__(16) float Bs[2][BK][BN];

    const int tid = threadIdx.x;
    const int bm  = blockIdx.y * BM;
    const int bn  = blockIdx.x * BN;
    const int tx  = tid & 15;      // 0..15  -> 8 cols each
    const int ty  = tid >> 4;      // 0..15  -> 8 rows each

    // A tile loader mapping: 512 float4 per tile, 2 per thread
    const int ar0 = tid >> 2;          // row 0..63
    const int aq0 = tid & 3;           // col quad 0..3
    const int ar1 = ar0 + 64;
    // B tile loader mapping
    const int bk0 = tid >> 5;          // 0..7
    const int bc0 = tid & 31;          // col quad 0..31
    const int bk1 = bk0 + 8;

    float acc[8][8] = {};

    float4 pa0, pa1, pb0, pb1;

    // prologue: load tile 0 into buffer 0
    pa0 = *(const float4*)(A + (size_t)(bm + ar0) * K + 0 * BK + aq0 * 4);
    pa1 = *(const float4*)(A + (size_t)(bm + ar1) * K + 0 * BK + aq0 * 4);
    pb0 = *(const float4*)(W + (size_t)(0 * BK + bk0) * N + bn + bc0 * 4);
    pb1 = *(const float4*)(W + (size_t)(0 * BK + bk1) * N + bn + bc0 * 4);

    As[0][aq0 * 4 + 0][ar0] = pa0.x;
    As[0][aq0 * 4 + 1][ar0] = pa0.y;
    As[0][aq0 * 4 + 2][ar0] = pa0.z;
    As[0][aq0 * 4 + 3][ar0] = pa0.w;
    As[0][aq0 * 4 + 0][ar1] = pa1.x;
    As[0][aq0 * 4 + 1][ar1] = pa1.y;
    As[0][aq0 * 4 + 2][ar1] = pa1.z;
    As[0][aq0 * 4 + 3][ar1] = pa1.w;
    *(float4*)&Bs[0][bk0][bc0 * 4] = pb0;
    *(float4*)&Bs[0][bk1][bc0 * 4] = pb1;
    __syncthreads();

    const int ntiles = K / BK;
    int buf = 0;
    for (int kt = 0; kt < ntiles; ++kt) {
        if (kt + 1 < ntiles) {
            const int k0 = (kt + 1) * BK;
            pa0 = *(const float4*)(A + (size_t)(bm + ar0) * K + k0 + aq0 * 4);
            pa1 = *(const float4*)(A + (size_t)(bm + ar1) * K + k0 + aq0 * 4);
            pb0 = *(const float4*)(W + (size_t)(k0 + bk0) * N + bn + bc0 * 4);
            pb1 = *(const float4*)(W + (size_t)(k0 + bk1) * N + bn + bc0 * 4);
        }

        #pragma unroll
        for (int kk = 0; kk < BK; ++kk) {
            float4 a0 = *(const float4*)&As[buf][kk][ty * 8];
            float4 a1 = *(const float4*)&As[buf][kk][ty * 8 + 4];
            float4 b0 = *(const float4*)&Bs[buf][kk][tx * 8];
            float4 b1 = *(const float4*)&Bs[buf][kk][tx * 8 + 4];
            float av[8] = {a0.x, a0.y, a0.z, a0.w, a1.x, a1.y, a1.z, a1.w};
            float bv[8] = {b0.x, b0.y, b0.z, b0.w, b1.x, b1.y, b1.z, b1.w};
            #pragma unroll
            for (int i = 0; i < 8; ++i)
                #pragma unroll
                for (int j = 0; j < 8; ++j)
                    acc[i][j] = fmaf(av[i], bv[j], acc[i][j]);
        }

        if (kt + 1 < ntiles) {
            const int nb = buf ^ 1;
            As[nb][aq0 * 4 + 0][ar0] = pa0.x;
            As[nb][aq0 * 4 + 1][ar0] = pa0.y;
            As[nb][aq0 * 4 + 2][ar0] = pa0.z;
            As[nb][aq0 * 4 + 3][ar0] = pa0.w;
            As[nb][aq0 * 4 + 0][ar1] = pa1.x;
            As[nb][aq0 * 4 + 1][ar1] = pa1.y;
            As[nb][aq0 * 4 + 2][ar1] = pa1.z;
            As[nb][aq0 * 4 + 3][ar1] = pa1.w;
            *(float4*)&Bs[nb][bk0][bc0 * 4] = pb0;
            *(float4*)&Bs[nb][bk1][bc0 * 4] = pb1;
        }
        __syncthreads();
        buf ^= 1;
    }

    // epilogue: add bias, store
    float bcol[8];
    #pragma unroll
    for (int j = 0; j < 8; ++j) bcol[j] = bias[bn + tx * 8 + j];

    #pragma unroll
    for (int i = 0; i < 8; ++i) {
        const int row = bm + ty * 8 + i;
        float* Cp = C + (size_t)row * N + bn + tx * 8;
        float4 o0 = make_float4(acc[i][0] + bcol[0], acc[i][1] + bcol[1],
                                acc[i][2] + bcol[2], acc[i][3] + bcol[3]);
        float4 o1 = make_float4(acc[i][4] + bcol[4], acc[i][5] + bcol[5],
                                acc[i][6] + bcol[6], acc[i][7] + bcol[7]);
        *(float4*)(Cp + 0) = o0;
        *(float4*)(Cp + 4) = o1;
    }
}

// ---------------- gather attention: one block per (b,q), one warp per head -
__global__ void __launch_bounds__(256) attn_kernel(
    const float* __restrict__ q, const float* __restrict__ k,
    const float* __restrict__ v, const int* __restrict__ indices,
    const float* __restrict__ weights, float* __restrict__ out)
{
    const int bq   = blockIdx.x;           // b*HW + pos
    const int b    = bq >> 12;             // HW = 4096
    const int warp = threadIdx.x >> 5;     // head
    const int lane = threadIdx.x & 31;

    const int   idx = indices[(size_t)bq * KNN + lane];
    const float w   = weights[(size_t)bq * KNN + lane];

    const float* kb = k + (size_t)b * NTGT * CC;
    const float* vb = v + (size_t)b * NTGT * CC;
    const int hoff  = warp * DH + 2 * lane;

    const float2 q2 = *(const float2*)(q + (size_t)bq * CC + hoff);

    float logit = -1e30f;
    #pragma unroll
    for (int j = 0; j < KNN; ++j) {
        const int ij = __shfl_sync(0xffffffffu, idx, j);
        const float2 k2 = *(const float2*)(kb + (size_t)ij * CC + hoff);
        float d = q2.x * k2.x + q2.y * k2.y;
        d += __shfl_xor_sync(0xffffffffu, d, 16);
        d += __shfl_xor_sync(0xffffffffu, d, 8);
        d += __shfl_xor_sync(0xffffffffu, d, 4);
        d += __shfl_xor_sync(0xffffffffu, d, 2);
        d += __shfl_xor_sync(0xffffffffu, d, 1);
        if (lane == j) logit = d * SCALE + w;
    }

    // warp softmax (KNN == 32 == warp width: one logit per lane)
    float m = logit;
    #pragma unroll
    for (int o = 16; o; o >>= 1) m = fmaxf(m, __shfl_xor_sync(0xffffffffu, m, o));
    float p = __expf(logit - m);
    float s = p;
    #pragma unroll
    for (int o = 16; o; o >>= 1) s += __shfl_xor_sync(0xffffffffu, s, o);
    p /= s;

    float2 acc = make_float2(0.f, 0.f);
    #pragma unroll
    for (int j = 0; j < KNN; ++j) {
        const float pj = __shfl_sync(0xffffffffu, p, j);
        const int ij = __shfl_sync(0xffffffffu, idx, j);
        const float2 v2 = *(const float2*)(vb + (size_t)ij * CC + hoff);
        acc.x = fmaf(pj, v2.x, acc.x);
        acc.y = fmaf(pj, v2.y, acc.y);
    }

    *(float2*)(out + (size_t)bq * CC + hoff) = acc;
}

// ---------------- launch ----------------------------------------------------
extern "C" void kernel_launch(void* const* d_in, const int* in_sizes, int n_in,
                              void* d_out, int out_size)
{
    const float* src = (const float*)d_in[0];
    const float* tgt = (const float*)d_in[1];
    const int*   idx = (const int*)d_in[2];
    const float* wts = (const float*)d_in[3];
    const float* Wq  = (const float*)d_in[4];
    const float* bq  = (const float*)d_in[5];
    const float* Wk  = (const float*)d_in[6];
    const float* bk  = (const float*)d_in[7];
    const float* Wv  = (const float*)d_in[8];
    const float* bv  = (const float*)d_in[9];
    const float* Wo  = (const float*)d_in[10];
    const float* bo  = (const float*)d_in[11];
    float*       out = (float*)d_out;

    void *pq, *pk, *pv, *pa;
    cudaGetSymbolAddress(&pq, g_q);
    cudaGetSymbolAddress(&pk, g_k);
    cudaGetSymbolAddress(&pv, g_v);
    cudaGetSymbolAddress(&pa, g_att);
    float* gq = (float*)pq;
    float* gk = (float*)pk;
    float* gv = (float*)pv;
    float* ga = (float*)pa;

    dim3 ggrid(CC / BN, MROWS / BM);   // (4, 64)
    sgemm_bias<<<ggrid, 256>>>(src, Wq, bq, gq, MROWS, CC, CC);
    sgemm_bias<<<ggrid, 256>>>(tgt, Wk, bk, gk, MROWS, CC, CC);
    sgemm_bias<<<ggrid, 256>>>(tgt, Wv, bv, gv, MROWS, CC, CC);

    attn_kernel<<<BB * HW, 256>>>(gq, gk, gv, idx, wts, ga);

    sgemm_bias<<<ggrid, 256>>>(ga, Wo, bo, out, MROWS, CC, CC);
}

// round 4
// speedup vs baseline: 1.0159x; 1.0159x over previous
#include <cuda_runtime.h>
#include <cuda_bf16.h>
#include <cstdint>

// Problem constants
#define BB    2
#define HW    4096
#define NTGT  4096
#define CC    512
#define HH    8
#define KNN   32
#define DH    64
#define MROWS (BB * HW)      // 8192
#define SCALE 0.125f

// ---------------- scratch (device globals: allocation-free) ----------------
__device__ float g_q[(size_t)MROWS * CC];
__device__ float g_k[(size_t)MROWS * CC];
__device__ float g_v[(size_t)MROWS * CC];
__device__ float g_att[(size_t)MROWS * CC];

// ---------------- packed f32x2 helpers (base sm_100+ PTX, not 'a'-gated) ---
__device__ __forceinline__ unsigned long long packf2(float x, float y) {
    unsigned long long r;
    asm("mov.b64 %0, {%1, %2};" : "=l"(r) : "f"(x), "f"(y));
    return r;
}
__device__ __forceinline__ void ffma2(unsigned long long& d,
                                      unsigned long long a,
                                      unsigned long long b) {
    asm("fma.rn.f32x2 %0, %1, %2, %0;" : "+l"(d) : "l"(a), "l"(b));
}
__device__ __forceinline__ float2 unpackf2(unsigned long long v) {
    float x, y;
    asm("mov.b64 {%0, %1}, %2;" : "=f"(x), "=f"(y) : "l"(v));
    return make_float2(x, y);
}

// ---------------- fp32x2 tiled GEMM: C[M,N] = A[M,K] @ W[K,N] + bias -------
#define BM 128
#define BN 128
#define BK 16

__global__ void __launch_bounds__(256, 2) sgemm_bias(
    const float* __restrict__ A, const float* __restrict__ W,
    const float* __restrict__ bias, float* __restrict__ C,
    int M, int N, int K)
{
    __shared__ __align__(16) float As[2][BK][BM];
    __shared__ __align__(16) float Bs[2][BK][BN];

    const int tid = threadIdx.x;
    const int bm  = blockIdx.y * BM;
    const int bn  = blockIdx.x * BN;
    const int tx  = tid & 15;      // 0..15  -> 8 cols each
    const int ty  = tid >> 4;      // 0..15  -> 8 rows each

    // A tile loader mapping: 512 float4 per tile, 2 per thread
    const int ar0 = tid >> 2;          // row 0..63
    const int aq0 = tid & 3;           // col quad 0..3
    const int ar1 = ar0 + 64;
    // B tile loader mapping
    const int bk0 = tid >> 5;          // 0..7
    const int bc0 = tid & 31;          // col quad 0..31
    const int bk1 = bk0 + 8;

    // packed accumulators: acc2[i][jp] = (C[i][2jp], C[i][2jp+1])
    unsigned long long acc2[8][4];
    #pragma unroll
    for (int i = 0; i < 8; ++i)
        #pragma unroll
        for (int jp = 0; jp < 4; ++jp) acc2[i][jp] = 0ull;

    float4 pa0, pa1, pb0, pb1;

    // prologue: load tile 0 into buffer 0
    pa0 = *(const float4*)(A + (size_t)(bm + ar0) * K + 0 * BK + aq0 * 4);
    pa1 = *(const float4*)(A + (size_t)(bm + ar1) * K + 0 * BK + aq0 * 4);
    pb0 = *(const float4*)(W + (size_t)(0 * BK + bk0) * N + bn + bc0 * 4);
    pb1 = *(const float4*)(W + (size_t)(0 * BK + bk1) * N + bn + bc0 * 4);

    As[0][aq0 * 4 + 0][ar0] = pa0.x;
    As[0][aq0 * 4 + 1][ar0] = pa0.y;
    As[0][aq0 * 4 + 2][ar0] = pa0.z;
    As[0][aq0 * 4 + 3][ar0] = pa0.w;
    As[0][aq0 * 4 + 0][ar1] = pa1.x;
    As[0][aq0 * 4 + 1][ar1] = pa1.y;
    As[0][aq0 * 4 + 2][ar1] = pa1.z;
    As[0][aq0 * 4 + 3][ar1] = pa1.w;
    *(float4*)&Bs[0][bk0][bc0 * 4] = pb0;
    *(float4*)&Bs[0][bk1][bc0 * 4] = pb1;
    __syncthreads();

    const int ntiles = K / BK;
    int buf = 0;
    for (int kt = 0; kt < ntiles; ++kt) {
        if (kt + 1 < ntiles) {
            const int k0 = (kt + 1) * BK;
            pa0 = *(const float4*)(A + (size_t)(bm + ar0) * K + k0 + aq0 * 4);
            pa1 = *(const float4*)(A + (size_t)(bm + ar1) * K + k0 + aq0 * 4);
            pb0 = *(const float4*)(W + (size_t)(k0 + bk0) * N + bn + bc0 * 4);
            pb1 = *(const float4*)(W + (size_t)(k0 + bk1) * N + bn + bc0 * 4);
        }

        #pragma unroll
        for (int kk = 0; kk < BK; ++kk) {
            float4 a0 = *(const float4*)&As[buf][kk][ty * 8];
            float4 a1 = *(const float4*)&As[buf][kk][ty * 8 + 4];
            float4 b0 = *(const float4*)&Bs[buf][kk][tx * 8];
            float4 b1 = *(const float4*)&Bs[buf][kk][tx * 8 + 4];

            unsigned long long bp[4];
            bp[0] = packf2(b0.x, b0.y);
            bp[1] = packf2(b0.z, b0.w);
            bp[2] = packf2(b1.x, b1.y);
            bp[3] = packf2(b1.z, b1.w);

            float av[8] = {a0.x, a0.y, a0.z, a0.w, a1.x, a1.y, a1.z, a1.w};
            #pragma unroll
            for (int i = 0; i < 8; ++i) {
                const unsigned long long ap = packf2(av[i], av[i]);
                #pragma unroll
                for (int jp = 0; jp < 4; ++jp)
                    ffma2(acc2[i][jp], ap, bp[jp]);
            }
        }

        if (kt + 1 < ntiles) {
            const int nb = buf ^ 1;
            As[nb][aq0 * 4 + 0][ar0] = pa0.x;
            As[nb][aq0 * 4 + 1][ar0] = pa0.y;
            As[nb][aq0 * 4 + 2][ar0] = pa0.z;
            As[nb][aq0 * 4 + 3][ar0] = pa0.w;
            As[nb][aq0 * 4 + 0][ar1] = pa1.x;
            As[nb][aq0 * 4 + 1][ar1] = pa1.y;
            As[nb][aq0 * 4 + 2][ar1] = pa1.z;
            As[nb][aq0 * 4 + 3][ar1] = pa1.w;
            *(float4*)&Bs[nb][bk0][bc0 * 4] = pb0;
            *(float4*)&Bs[nb][bk1][bc0 * 4] = pb1;
        }
        __syncthreads();
        buf ^= 1;
    }

    // epilogue: add bias, store
    float bcol[8];
    #pragma unroll
    for (int j = 0; j < 8; ++j) bcol[j] = bias[bn + tx * 8 + j];

    #pragma unroll
    for (int i = 0; i < 8; ++i) {
        const int row = bm + ty * 8 + i;
        float* Cp = C + (size_t)row * N + bn + tx * 8;
        float2 c0 = unpackf2(acc2[i][0]);
        float2 c1 = unpackf2(acc2[i][1]);
        float2 c2 = unpackf2(acc2[i][2]);
        float2 c3 = unpackf2(acc2[i][3]);
        float4 o0 = make_float4(c0.x + bcol[0], c0.y + bcol[1],
                                c1.x + bcol[2], c1.y + bcol[3]);
        float4 o1 = make_float4(c2.x + bcol[4], c2.y + bcol[5],
                                c3.x + bcol[6], c3.y + bcol[7]);
        *(float4*)(Cp + 0) = o0;
        *(float4*)(Cp + 4) = o1;
    }
}

// ---------------- gather attention: one block per (b,q), one warp per head -
__global__ void __launch_bounds__(256) attn_kernel(
    const float* __restrict__ q, const float* __restrict__ k,
    const float* __restrict__ v, const int* __restrict__ indices,
    const float* __restrict__ weights, float* __restrict__ out)
{
    const int bq   = blockIdx.x;           // b*HW + pos
    const int b    = bq >> 12;             // HW = 4096
    const int warp = threadIdx.x >> 5;     // head
    const int lane = threadIdx.x & 31;

    const int   idx = indices[(size_t)bq * KNN + lane];
    const float w   = weights[(size_t)bq * KNN + lane];

    const float* kb = k + (size_t)b * NTGT * CC;
    const float* vb = v + (size_t)b * NTGT * CC;
    const int hoff  = warp * DH + 2 * lane;

    const float2 q2 = *(const float2*)(q + (size_t)bq * CC + hoff);

    float logit = -1e30f;
    #pragma unroll
    for (int j = 0; j < KNN; ++j) {
        const int ij = __shfl_sync(0xffffffffu, idx, j);
        const float2 k2 = *(const float2*)(kb + (size_t)ij * CC + hoff);
        float d = q2.x * k2.x + q2.y * k2.y;
        d += __shfl_xor_sync(0xffffffffu, d, 16);
        d += __shfl_xor_sync(0xffffffffu, d, 8);
        d += __shfl_xor_sync(0xffffffffu, d, 4);
        d += __shfl_xor_sync(0xffffffffu, d, 2);
        d += __shfl_xor_sync(0xffffffffu, d, 1);
        if (lane == j) logit = d * SCALE + w;
    }

    // warp softmax (KNN == 32 == warp width: one logit per lane)
    float m = logit;
    #pragma unroll
    for (int o = 16; o; o >>= 1) m = fmaxf(m, __shfl_xor_sync(0xffffffffu, m, o));
    float p = __expf(logit - m);
    float s = p;
    #pragma unroll
    for (int o = 16; o; o >>= 1) s += __shfl_xor_sync(0xffffffffu, s, o);
    p /= s;

    float2 acc = make_float2(0.f, 0.f);
    #pragma unroll
    for (int j = 0; j < KNN; ++j) {
        const float pj = __shfl_sync(0xffffffffu, p, j);
        const int ij = __shfl_sync(0xffffffffu, idx, j);
        const float2 v2 = *(const float2*)(vb + (size_t)ij * CC + hoff);
        acc.x = fmaf(pj, v2.x, acc.x);
        acc.y = fmaf(pj, v2.y, acc.y);
    }

    *(float2*)(out + (size_t)bq * CC + hoff) = acc;
}

// ---------------- launch ----------------------------------------------------
extern "C" void kernel_launch(void* const* d_in, const int* in_sizes, int n_in,
                              void* d_out, int out_size)
{
    const float* src = (const float*)d_in[0];
    const float* tgt = (const float*)d_in[1];
    const int*   idx = (const int*)d_in[2];
    const float* wts = (const float*)d_in[3];
    const float* Wq  = (const float*)d_in[4];
    const float* bq  = (const float*)d_in[5];
    const float* Wk  = (const float*)d_in[6];
    const float* bk  = (const float*)d_in[7];
    const float* Wv  = (const float*)d_in[8];
    const float* bv  = (const float*)d_in[9];
    const float* Wo  = (const float*)d_in[10];
    const float* bo  = (const float*)d_in[11];
    float*       out = (float*)d_out;

    void *pq, *pk, *pv, *pa;
    cudaGetSymbolAddress(&pq, g_q);
    cudaGetSymbolAddress(&pk, g_k);
    cudaGetSymbolAddress(&pv, g_v);
    cudaGetSymbolAddress(&pa, g_att);
    float* gq = (float*)pq;
    float* gk = (float*)pk;
    float* gv = (float*)pv;
    float* ga = (float*)pa;

    dim3 ggrid(CC / BN, MROWS / BM);   // (4, 64)
    sgemm_bias<<<ggrid, 256>>>(src, Wq, bq, gq, MROWS, CC, CC);
    sgemm_bias<<<ggrid, 256>>>(tgt, Wk, bk, gk, MROWS, CC, CC);
    sgemm_bias<<<ggrid, 256>>>(tgt, Wv, bv, gv, MROWS, CC, CC);

    attn_kernel<<<BB * HW, 256>>>(gq, gk, gv, idx, wts, ga);

    sgemm_bias<<<ggrid, 256>>>(ga, Wo, bo, out, MROWS, CC, CC);
}

// round 5
// speedup vs baseline: 1.8478x; 1.8189x over previous
#include <cuda_runtime.h>
#include <cuda_bf16.h>
#include <cstdint>

// Problem constants
#define BB    2
#define HW    4096
#define NTGT  4096
#define CC    512
#define HH    8
#define KNN   32
#define DH    64
#define MROWS (BB * HW)      // 8192
#define SCALE 0.125f

// ---------------- scratch (device globals: allocation-free) ----------------
__device__ float g_q[(size_t)MROWS * CC];
__device__ float g_k[(size_t)MROWS * CC];
__device__ float g_v[(size_t)MROWS * CC];
__device__ float g_att[(size_t)MROWS * CC];
__device__ __nv_bfloat16 g_Ahi[(size_t)MROWS * CC];
__device__ __nv_bfloat16 g_Alo[(size_t)MROWS * CC];
__device__ __nv_bfloat16 g_Wt_hi[4][CC * CC];   // [N][K]
__device__ __nv_bfloat16 g_Wt_lo[4][CC * CC];

// ---------------- helpers ----------------------------------------------------
__device__ __forceinline__ uint32_t smem_to_u32(const void* p) {
    uint32_t a;
    asm("{ .reg .u64 t; cvta.to.shared.u64 t, %1; cvt.u32.u64 %0, t; }"
        : "=r"(a) : "l"(p));
    return a;
}
__device__ __forceinline__ void cp16(uint32_t dst, const void* src) {
    asm volatile("cp.async.cg.shared.global [%0], [%1], 16;" :: "r"(dst), "l"(src));
}
#define CP_COMMIT() asm volatile("cp.async.commit_group;" ::: "memory")
#define CP_WAIT(n)  asm volatile("cp.async.wait_group %0;" :: "n"(n) : "memory")

__device__ __forceinline__ uint32_t pack2(__nv_bfloat16 a, __nv_bfloat16 b) {
    __nv_bfloat162 t; t.x = a; t.y = b;
    return *reinterpret_cast<uint32_t*>(&t);
}

// ---------------- weight transpose + bf16 split: W[K][N] -> Wt[N][K] --------
__global__ void transpose_split_kernel(const float* __restrict__ W,
                                       __nv_bfloat16* __restrict__ hi,
                                       __nv_bfloat16* __restrict__ lo)
{
    __shared__ float t[32][33];
    const int kt = blockIdx.x * 32;
    const int nt = blockIdx.y * 32;
    const int tx = threadIdx.x, ty = threadIdx.y;  // (32, 8)
    #pragma unroll
    for (int i = 0; i < 4; ++i)
        t[ty + i * 8][tx] = W[(size_t)(kt + ty + i * 8) * CC + nt + tx];
    __syncthreads();
    #pragma unroll
    for (int i = 0; i < 4; ++i) {
        float x = t[tx][ty + i * 8];
        __nv_bfloat16 h = __float2bfloat16_rn(x);
        __nv_bfloat16 l = __float2bfloat16_rn(x - __bfloat162float(h));
        size_t o = (size_t)(nt + ty + i * 8) * CC + kt + tx;
        hi[o] = h;
        lo[o] = l;
    }
}

// ---------------- activation split: f32 -> bf16 hi/lo -----------------------
__global__ void __launch_bounds__(256) split_bf16_kernel(
    const float* __restrict__ X,
    __nv_bfloat16* __restrict__ hi, __nv_bfloat16* __restrict__ lo)
{
    const int i = blockIdx.x * 256 + threadIdx.x;     // one float4 each
    const float4 x = reinterpret_cast<const float4*>(X)[i];
    __nv_bfloat16 h0 = __float2bfloat16_rn(x.x);
    __nv_bfloat16 h1 = __float2bfloat16_rn(x.y);
    __nv_bfloat16 h2 = __float2bfloat16_rn(x.z);
    __nv_bfloat16 h3 = __float2bfloat16_rn(x.w);
    __nv_bfloat16 l0 = __float2bfloat16_rn(x.x - __bfloat162float(h0));
    __nv_bfloat16 l1 = __float2bfloat16_rn(x.y - __bfloat162float(h1));
    __nv_bfloat16 l2 = __float2bfloat16_rn(x.z - __bfloat162float(h2));
    __nv_bfloat16 l3 = __float2bfloat16_rn(x.w - __bfloat162float(h3));
    reinterpret_cast<uint2*>(hi)[i] = make_uint2(pack2(h0, h1), pack2(h2, h3));
    reinterpret_cast<uint2*>(lo)[i] = make_uint2(pack2(l0, l1), pack2(l2, l3));
}

// ---------------- bf16 mma.sync GEMM: C = A @ Wt^T + bias -------------------
// A hi/lo [M][K] bf16, Wt hi/lo [N][K] bf16, 3-term split, f32 accum.
// CTA 128x128, BK=32, 8 warps (2x4), warp tile 64x32, cp.async double buffer.
#define ROWB 80                    // smem row stride bytes (64 data + 16 pad)
#define STG  (128 * ROWB)          // 10240 per half-stage
#define OFF_AHI 0
#define OFF_ALO (2 * STG)
#define OFF_BHI (4 * STG)
#define OFF_BLO (6 * STG)
#define SM_TOT  (8 * STG)          // 81920 B

__global__ void __launch_bounds__(256, 2) mma_gemm_bias(
    const __nv_bfloat16* __restrict__ Ahi, const __nv_bfloat16* __restrict__ Alo,
    const __nv_bfloat16* __restrict__ Whi, const __nv_bfloat16* __restrict__ Wlo,
    const float* __restrict__ bias, float* __restrict__ C)
{
    extern __shared__ char sm[];
    const uint32_t sb = smem_to_u32(sm);
    const int tid  = threadIdx.x;
    const int wid  = tid >> 5;
    const int lane = tid & 31;
    const int bm   = blockIdx.y * 128;
    const int bn   = blockIdx.x * 128;
    const int wm   = wid & 1;          // 0..1
    const int wn   = wid >> 1;         // 0..3

    // loader mapping: per array per stage, 512 x 16B chunks; 2 per thread
    const int lr = tid >> 2;           // row 0..63 (chunk adds +64)
    const int lq = tid & 3;            // 16B quad within 64B row

    float acc[4][4][4];
    #pragma unroll
    for (int a = 0; a < 4; ++a)
        #pragma unroll
        for (int b = 0; b < 4; ++b)
            #pragma unroll
            for (int c = 0; c < 4; ++c) acc[a][b][c] = 0.f;

    // stage loader
    auto load_stage = [&](int s, int kt) {
        const int kb = kt * 32;        // k element offset
        #pragma unroll
        for (int c = 0; c < 2; ++c) {
            const int row = c * 64 + lr;
            const uint32_t so = (uint32_t)(row * ROWB + lq * 16 + s * STG);
            const size_t  ga = (size_t)(bm + row) * CC + kb + lq * 8;
            const size_t  gb = (size_t)(bn + row) * CC + kb + lq * 8;
            cp16(sb + OFF_AHI + so, Ahi + ga);
            cp16(sb + OFF_ALO + so, Alo + ga);
            cp16(sb + OFF_BHI + so, Whi + gb);
            cp16(sb + OFF_BLO + so, Wlo + gb);
        }
    };

    load_stage(0, 0);
    CP_COMMIT();

    const int sub16 = lane & 15;
    const int ahalf = lane >> 4;                 // 0/1 -> k-byte +0/+16
    const int bsub  = lane & 15;
    const int bn8   = bsub & 7;
    const int bk16  = (bsub >> 3) & 1;           // +16B for second 8 lanes

    #pragma unroll 1
    for (int kt = 0; kt < 16; ++kt) {
        const int s = kt & 1;
        if (kt + 1 < 16) {
            load_stage(s ^ 1, kt + 1);
            CP_COMMIT();
            CP_WAIT(1);
        } else {
            CP_WAIT(0);
        }
        __syncthreads();

        #pragma unroll
        for (int s2 = 0; s2 < 2; ++s2) {
            const int kbyte = s2 * 32;
            // ---- B fragments (held): 4 nfrags x (hi,lo), ldmatrix.x2 ----
            uint32_t bh[4][2], bl[4][2];
            #pragma unroll
            for (int nf = 0; nf < 4; ++nf) {
                const uint32_t brow = (uint32_t)(wn * 32 + nf * 8 + bn8);
                const uint32_t ba = sb + (uint32_t)(s * STG) + brow * ROWB
                                  + kbyte + bk16 * 16;
                asm volatile(
                    "ldmatrix.sync.aligned.m8n8.x2.shared.b16 {%0,%1}, [%2];"
                    : "=r"(bh[nf][0]), "=r"(bh[nf][1]) : "r"(ba + OFF_BHI));
                asm volatile(
                    "ldmatrix.sync.aligned.m8n8.x2.shared.b16 {%0,%1}, [%2];"
                    : "=r"(bl[nf][0]), "=r"(bl[nf][1]) : "r"(ba + OFF_BLO));
            }
            // ---- A fragments per mfrag, 3-term mma ----
            #pragma unroll
            for (int mf = 0; mf < 4; ++mf) {
                const uint32_t arow = (uint32_t)(wm * 64 + mf * 16 + sub16);
                const uint32_t aa = sb + (uint32_t)(s * STG) + arow * ROWB
                                  + kbyte + ahalf * 16;
                uint32_t ah[4], al[4];
                asm volatile(
                    "ldmatrix.sync.aligned.m8n8.x4.shared.b16 {%0,%1,%2,%3}, [%4];"
                    : "=r"(ah[0]), "=r"(ah[1]), "=r"(ah[2]), "=r"(ah[3])
                    : "r"(aa + OFF_AHI));
                asm volatile(
                    "ldmatrix.sync.aligned.m8n8.x4.shared.b16 {%0,%1,%2,%3}, [%4];"
                    : "=r"(al[0]), "=r"(al[1]), "=r"(al[2]), "=r"(al[3])
                    : "r"(aa + OFF_ALO));
                #pragma unroll
                for (int nf = 0; nf < 4; ++nf) {
                    float* d = acc[mf][nf];
                    asm volatile(
                        "mma.sync.aligned.m16n8k16.row.col.f32.bf16.bf16.f32 "
                        "{%0,%1,%2,%3}, {%4,%5,%6,%7}, {%8,%9}, {%0,%1,%2,%3};"
                        : "+f"(d[0]), "+f"(d[1]), "+f"(d[2]), "+f"(d[3])
                        : "r"(ah[0]), "r"(ah[1]), "r"(ah[2]), "r"(ah[3]),
                          "r"(bh[nf][0]), "r"(bh[nf][1]));
                    asm volatile(
                        "mma.sync.aligned.m16n8k16.row.col.f32.bf16.bf16.f32 "
                        "{%0,%1,%2,%3}, {%4,%5,%6,%7}, {%8,%9}, {%0,%1,%2,%3};"
                        : "+f"(d[0]), "+f"(d[1]), "+f"(d[2]), "+f"(d[3])
                        : "r"(ah[0]), "r"(ah[1]), "r"(ah[2]), "r"(ah[3]),
                          "r"(bl[nf][0]), "r"(bl[nf][1]));
                    asm volatile(
                        "mma.sync.aligned.m16n8k16.row.col.f32.bf16.bf16.f32 "
                        "{%0,%1,%2,%3}, {%4,%5,%6,%7}, {%8,%9}, {%0,%1,%2,%3};"
                        : "+f"(d[0]), "+f"(d[1]), "+f"(d[2]), "+f"(d[3])
                        : "r"(al[0]), "r"(al[1]), "r"(al[2]), "r"(al[3]),
                          "r"(bh[nf][0]), "r"(bh[nf][1]));
                }
            }
        }
        __syncthreads();
    }

    // ---- epilogue ----
    const int g = lane >> 2;
    const int t = lane & 3;
    #pragma unroll
    for (int mf = 0; mf < 4; ++mf) {
        const int row = bm + wm * 64 + mf * 16 + g;
        #pragma unroll
        for (int nf = 0; nf < 4; ++nf) {
            const int col = bn + wn * 32 + nf * 8 + 2 * t;
            const float b0 = __ldg(bias + col);
            const float b1 = __ldg(bias + col + 1);
            float* d = acc[mf][nf];
            *reinterpret_cast<float2*>(C + (size_t)row * CC + col) =
                make_float2(d[0] + b0, d[1] + b1);
            *reinterpret_cast<float2*>(C + (size_t)(row + 8) * CC + col) =
                make_float2(d[2] + b0, d[3] + b1);
        }
    }
}

// ---------------- gather attention (unchanged, known-good) ------------------
__global__ void __launch_bounds__(256) attn_kernel(
    const float* __restrict__ q, const float* __restrict__ k,
    const float* __restrict__ v, const int* __restrict__ indices,
    const float* __restrict__ weights, float* __restrict__ out)
{
    const int bq   = blockIdx.x;
    const int b    = bq >> 12;
    const int warp = threadIdx.x >> 5;
    const int lane = threadIdx.x & 31;

    const int   idx = indices[(size_t)bq * KNN + lane];
    const float w   = weights[(size_t)bq * KNN + lane];

    const float* kb = k + (size_t)b * NTGT * CC;
    const float* vb = v + (size_t)b * NTGT * CC;
    const int hoff  = warp * DH + 2 * lane;

    const float2 q2 = *(const float2*)(q + (size_t)bq * CC + hoff);

    float logit = -1e30f;
    #pragma unroll
    for (int j = 0; j < KNN; ++j) {
        const int ij = __shfl_sync(0xffffffffu, idx, j);
        const float2 k2 = *(const float2*)(kb + (size_t)ij * CC + hoff);
        float d = q2.x * k2.x + q2.y * k2.y;
        d += __shfl_xor_sync(0xffffffffu, d, 16);
        d += __shfl_xor_sync(0xffffffffu, d, 8);
        d += __shfl_xor_sync(0xffffffffu, d, 4);
        d += __shfl_xor_sync(0xffffffffu, d, 2);
        d += __shfl_xor_sync(0xffffffffu, d, 1);
        if (lane == j) logit = d * SCALE + w;
    }

    float m = logit;
    #pragma unroll
    for (int o = 16; o; o >>= 1) m = fmaxf(m, __shfl_xor_sync(0xffffffffu, m, o));
    float p = __expf(logit - m);
    float s = p;
    #pragma unroll
    for (int o = 16; o; o >>= 1) s += __shfl_xor_sync(0xffffffffu, s, o);
    p /= s;

    float2 acc = make_float2(0.f, 0.f);
    #pragma unroll
    for (int j = 0; j < KNN; ++j) {
        const float pj = __shfl_sync(0xffffffffu, p, j);
        const int ij = __shfl_sync(0xffffffffu, idx, j);
        const float2 v2 = *(const float2*)(vb + (size_t)ij * CC + hoff);
        acc.x = fmaf(pj, v2.x, acc.x);
        acc.y = fmaf(pj, v2.y, acc.y);
    }

    *(float2*)(out + (size_t)bq * CC + hoff) = acc;
}

// ---------------- launch ----------------------------------------------------
extern "C" void kernel_launch(void* const* d_in, const int* in_sizes, int n_in,
                              void* d_out, int out_size)
{
    const float* src = (const float*)d_in[0];
    const float* tgt = (const float*)d_in[1];
    const int*   idx = (const int*)d_in[2];
    const float* wts = (const float*)d_in[3];
    const float* Wq  = (const float*)d_in[4];
    const float* bq  = (const float*)d_in[5];
    const float* Wk  = (const float*)d_in[6];
    const float* bk  = (const float*)d_in[7];
    const float* Wv  = (const float*)d_in[8];
    const float* bv  = (const float*)d_in[9];
    const float* Wo  = (const float*)d_in[10];
    const float* bo  = (const float*)d_in[11];
    float*       out = (float*)d_out;

    void *pq, *pk, *pv, *pa, *pahi, *palo, *pwhi, *pwlo;
    cudaGetSymbolAddress(&pq, g_q);
    cudaGetSymbolAddress(&pk, g_k);
    cudaGetSymbolAddress(&pv, g_v);
    cudaGetSymbolAddress(&pa, g_att);
    cudaGetSymbolAddress(&pahi, g_Ahi);
    cudaGetSymbolAddress(&palo, g_Alo);
    cudaGetSymbolAddress(&pwhi, g_Wt_hi);
    cudaGetSymbolAddress(&pwlo, g_Wt_lo);
    float* gq = (float*)pq;
    float* gk = (float*)pk;
    float* gv = (float*)pv;
    float* ga = (float*)pa;
    __nv_bfloat16* ahi = (__nv_bfloat16*)pahi;
    __nv_bfloat16* alo = (__nv_bfloat16*)palo;
    __nv_bfloat16* whi = (__nv_bfloat16*)pwhi;
    __nv_bfloat16* wlo = (__nv_bfloat16*)pwlo;

    static bool attr_set = false;
    if (!attr_set) {
        cudaFuncSetAttribute(mma_gemm_bias,
                             cudaFuncAttributeMaxDynamicSharedMemorySize, SM_TOT);
        attr_set = true;
    }

    const size_t WS = (size_t)CC * CC;
    dim3 tgrid(CC / 32, CC / 32), tblk(32, 8);
    transpose_split_kernel<<<tgrid, tblk>>>(Wq, whi + 0 * WS, wlo + 0 * WS);
    transpose_split_kernel<<<tgrid, tblk>>>(Wk, whi + 1 * WS, wlo + 1 * WS);
    transpose_split_kernel<<<tgrid, tblk>>>(Wv, whi + 2 * WS, wlo + 2 * WS);
    transpose_split_kernel<<<tgrid, tblk>>>(Wo, whi + 3 * WS, wlo + 3 * WS);

    const int nsplit = MROWS * CC / 4 / 256;   // 4096 blocks
    dim3 ggrid(CC / 128, MROWS / 128);         // (4, 64)

    split_bf16_kernel<<<nsplit, 256>>>(src, ahi, alo);
    mma_gemm_bias<<<ggrid, 256, SM_TOT>>>(ahi, alo, whi + 0 * WS, wlo + 0 * WS, bq, gq);

    split_bf16_kernel<<<nsplit, 256>>>(tgt, ahi, alo);
    mma_gemm_bias<<<ggrid, 256, SM_TOT>>>(ahi, alo, whi + 1 * WS, wlo + 1 * WS, bk, gk);
    mma_gemm_bias<<<ggrid, 256, SM_TOT>>>(ahi, alo, whi + 2 * WS, wlo + 2 * WS, bv, gv);

    attn_kernel<<<BB * HW, 256>>>(gq, gk, gv, idx, wts, ga);

    split_bf16_kernel<<<nsplit, 256>>>(ga, ahi, alo);
    mma_gemm_bias<<<ggrid, 256, SM_TOT>>>(ahi, alo, whi + 3 * WS, wlo + 3 * WS, bo, out);
}

// round 6
// speedup vs baseline: 2.1065x; 1.1400x over previous
#include <cuda_runtime.h>
#include <cuda_bf16.h>
#include <cstdint>

// Problem constants
#define BB    2
#define HW    4096
#define NTGT  4096
#define CC    512
#define HH    8
#define KNN   32
#define DH    64
#define MROWS (BB * HW)      // 8192
#define SCALE 0.125f

// ---------------- scratch (device globals: allocation-free) ----------------
__device__ float g_q[(size_t)MROWS * CC];
__device__ float g_k[(size_t)MROWS * CC];
__device__ float g_v[(size_t)MROWS * CC];
__device__ __nv_bfloat16 g_Shi[(size_t)MROWS * CC];  // src split
__device__ __nv_bfloat16 g_Slo[(size_t)MROWS * CC];
__device__ __nv_bfloat16 g_Thi[(size_t)MROWS * CC];  // tgt split
__device__ __nv_bfloat16 g_Tlo[(size_t)MROWS * CC];
__device__ __nv_bfloat16 g_Ohi[(size_t)MROWS * CC];  // attn-out split
__device__ __nv_bfloat16 g_Olo[(size_t)MROWS * CC];
__device__ __nv_bfloat16 g_Wt_hi[4][CC * CC];        // [N][K]
__device__ __nv_bfloat16 g_Wt_lo[4][CC * CC];

// ---------------- helpers ----------------------------------------------------
__device__ __forceinline__ uint32_t smem_to_u32(const void* p) {
    uint32_t a;
    asm("{ .reg .u64 t; cvta.to.shared.u64 t, %1; cvt.u32.u64 %0, t; }"
        : "=r"(a) : "l"(p));
    return a;
}
__device__ __forceinline__ void cp16(uint32_t dst, const void* src) {
    asm volatile("cp.async.cg.shared.global [%0], [%1], 16;" :: "r"(dst), "l"(src));
}
#define CP_COMMIT() asm volatile("cp.async.commit_group;" ::: "memory")
#define CP_WAIT(n)  asm volatile("cp.async.wait_group %0;" :: "n"(n) : "memory")

__device__ __forceinline__ uint32_t pack2(__nv_bfloat16 a, __nv_bfloat16 b) {
    __nv_bfloat162 t; t.x = a; t.y = b;
    return *reinterpret_cast<uint32_t*>(&t);
}

// ---------------- fused weight transpose + split (all 4 weights) ------------
__global__ void transpose_split_all(const float* __restrict__ W0,
                                    const float* __restrict__ W1,
                                    const float* __restrict__ W2,
                                    const float* __restrict__ W3,
                                    __nv_bfloat16* __restrict__ hi,
                                    __nv_bfloat16* __restrict__ lo)
{
    __shared__ float t[32][33];
    const int w  = blockIdx.z;
    const float* W = (w == 0) ? W0 : (w == 1) ? W1 : (w == 2) ? W2 : W3;
    const size_t wo = (size_t)w * CC * CC;
    const int kt = blockIdx.x * 32;
    const int nt = blockIdx.y * 32;
    const int tx = threadIdx.x, ty = threadIdx.y;  // (32, 8)
    #pragma unroll
    for (int i = 0; i < 4; ++i)
        t[ty + i * 8][tx] = W[(size_t)(kt + ty + i * 8) * CC + nt + tx];
    __syncthreads();
    #pragma unroll
    for (int i = 0; i < 4; ++i) {
        float x = t[tx][ty + i * 8];
        __nv_bfloat16 h = __float2bfloat16_rn(x);
        __nv_bfloat16 l = __float2bfloat16_rn(x - __bfloat162float(h));
        size_t o = wo + (size_t)(nt + ty + i * 8) * CC + kt + tx;
        hi[o] = h;
        lo[o] = l;
    }
}

// ---------------- fused activation split: src + tgt -------------------------
__global__ void __launch_bounds__(256) split2_kernel(
    const float* __restrict__ S, const float* __restrict__ T,
    __nv_bfloat16* __restrict__ shi, __nv_bfloat16* __restrict__ slo,
    __nv_bfloat16* __restrict__ thi, __nv_bfloat16* __restrict__ tlo)
{
    const int half = gridDim.x >> 1;
    const bool is_t = blockIdx.x >= half;
    const float* X = is_t ? T : S;
    __nv_bfloat16* hi = is_t ? thi : shi;
    __nv_bfloat16* lo = is_t ? tlo : slo;
    const int i = (is_t ? blockIdx.x - half : blockIdx.x) * 256 + threadIdx.x;
    const float4 x = reinterpret_cast<const float4*>(X)[i];
    __nv_bfloat16 h0 = __float2bfloat16_rn(x.x);
    __nv_bfloat16 h1 = __float2bfloat16_rn(x.y);
    __nv_bfloat16 h2 = __float2bfloat16_rn(x.z);
    __nv_bfloat16 h3 = __float2bfloat16_rn(x.w);
    __nv_bfloat16 l0 = __float2bfloat16_rn(x.x - __bfloat162float(h0));
    __nv_bfloat16 l1 = __float2bfloat16_rn(x.y - __bfloat162float(h1));
    __nv_bfloat16 l2 = __float2bfloat16_rn(x.z - __bfloat162float(h2));
    __nv_bfloat16 l3 = __float2bfloat16_rn(x.w - __bfloat162float(h3));
    reinterpret_cast<uint2*>(hi)[i] = make_uint2(pack2(h0, h1), pack2(h2, h3));
    reinterpret_cast<uint2*>(lo)[i] = make_uint2(pack2(l0, l1), pack2(l2, l3));
}

// ---------------- bf16 mma.sync GEMM (unchanged from R5, proven) ------------
#define ROWB 80
#define STG  (128 * ROWB)
#define OFF_AHI 0
#define OFF_ALO (2 * STG)
#define OFF_BHI (4 * STG)
#define OFF_BLO (6 * STG)
#define SM_TOT  (8 * STG)

__global__ void __launch_bounds__(256, 2) mma_gemm_bias(
    const __nv_bfloat16* __restrict__ Ahi, const __nv_bfloat16* __restrict__ Alo,
    const __nv_bfloat16* __restrict__ Whi, const __nv_bfloat16* __restrict__ Wlo,
    const float* __restrict__ bias, float* __restrict__ C)
{
    extern __shared__ char sm[];
    const uint32_t sb = smem_to_u32(sm);
    const int tid  = threadIdx.x;
    const int wid  = tid >> 5;
    const int lane = tid & 31;
    const int bm   = blockIdx.y * 128;
    const int bn   = blockIdx.x * 128;
    const int wm   = wid & 1;
    const int wn   = wid >> 1;

    const int lr = tid >> 2;
    const int lq = tid & 3;

    float acc[4][4][4];
    #pragma unroll
    for (int a = 0; a < 4; ++a)
        #pragma unroll
        for (int b = 0; b < 4; ++b)
            #pragma unroll
            for (int c = 0; c < 4; ++c) acc[a][b][c] = 0.f;

    auto load_stage = [&](int s, int kt) {
        const int kb = kt * 32;
        #pragma unroll
        for (int c = 0; c < 2; ++c) {
            const int row = c * 64 + lr;
            const uint32_t so = (uint32_t)(row * ROWB + lq * 16 + s * STG);
            const size_t  ga = (size_t)(bm + row) * CC + kb + lq * 8;
            const size_t  gb = (size_t)(bn + row) * CC + kb + lq * 8;
            cp16(sb + OFF_AHI + so, Ahi + ga);
            cp16(sb + OFF_ALO + so, Alo + ga);
            cp16(sb + OFF_BHI + so, Whi + gb);
            cp16(sb + OFF_BLO + so, Wlo + gb);
        }
    };

    load_stage(0, 0);
    CP_COMMIT();

    const int sub16 = lane & 15;
    const int ahalf = lane >> 4;
    const int bsub  = lane & 15;
    const int bn8   = bsub & 7;
    const int bk16  = (bsub >> 3) & 1;

    #pragma unroll 1
    for (int kt = 0; kt < 16; ++kt) {
        const int s = kt & 1;
        if (kt + 1 < 16) {
            load_stage(s ^ 1, kt + 1);
            CP_COMMIT();
            CP_WAIT(1);
        } else {
            CP_WAIT(0);
        }
        __syncthreads();

        #pragma unroll
        for (int s2 = 0; s2 < 2; ++s2) {
            const int kbyte = s2 * 32;
            uint32_t bh[4][2], bl[4][2];
            #pragma unroll
            for (int nf = 0; nf < 4; ++nf) {
                const uint32_t brow = (uint32_t)(wn * 32 + nf * 8 + bn8);
                const uint32_t ba = sb + (uint32_t)(s * STG) + brow * ROWB
                                  + kbyte + bk16 * 16;
                asm volatile(
                    "ldmatrix.sync.aligned.m8n8.x2.shared.b16 {%0,%1}, [%2];"
                    : "=r"(bh[nf][0]), "=r"(bh[nf][1]) : "r"(ba + OFF_BHI));
                asm volatile(
                    "ldmatrix.sync.aligned.m8n8.x2.shared.b16 {%0,%1}, [%2];"
                    : "=r"(bl[nf][0]), "=r"(bl[nf][1]) : "r"(ba + OFF_BLO));
            }
            #pragma unroll
            for (int mf = 0; mf < 4; ++mf) {
                const uint32_t arow = (uint32_t)(wm * 64 + mf * 16 + sub16);
                const uint32_t aa = sb + (uint32_t)(s * STG) + arow * ROWB
                                  + kbyte + ahalf * 16;
                uint32_t ah[4], al[4];
                asm volatile(
                    "ldmatrix.sync.aligned.m8n8.x4.shared.b16 {%0,%1,%2,%3}, [%4];"
                    : "=r"(ah[0]), "=r"(ah[1]), "=r"(ah[2]), "=r"(ah[3])
                    : "r"(aa + OFF_AHI));
                asm volatile(
                    "ldmatrix.sync.aligned.m8n8.x4.shared.b16 {%0,%1,%2,%3}, [%4];"
                    : "=r"(al[0]), "=r"(al[1]), "=r"(al[2]), "=r"(al[3])
                    : "r"(aa + OFF_ALO));
                #pragma unroll
                for (int nf = 0; nf < 4; ++nf) {
                    float* d = acc[mf][nf];
                    asm volatile(
                        "mma.sync.aligned.m16n8k16.row.col.f32.bf16.bf16.f32 "
                        "{%0,%1,%2,%3}, {%4,%5,%6,%7}, {%8,%9}, {%0,%1,%2,%3};"
                        : "+f"(d[0]), "+f"(d[1]), "+f"(d[2]), "+f"(d[3])
                        : "r"(ah[0]), "r"(ah[1]), "r"(ah[2]), "r"(ah[3]),
                          "r"(bh[nf][0]), "r"(bh[nf][1]));
                    asm volatile(
                        "mma.sync.aligned.m16n8k16.row.col.f32.bf16.bf16.f32 "
                        "{%0,%1,%2,%3}, {%4,%5,%6,%7}, {%8,%9}, {%0,%1,%2,%3};"
                        : "+f"(d[0]), "+f"(d[1]), "+f"(d[2]), "+f"(d[3])
                        : "r"(ah[0]), "r"(ah[1]), "r"(ah[2]), "r"(ah[3]),
                          "r"(bl[nf][0]), "r"(bl[nf][1]));
                    asm volatile(
                        "mma.sync.aligned.m16n8k16.row.col.f32.bf16.bf16.f32 "
                        "{%0,%1,%2,%3}, {%4,%5,%6,%7}, {%8,%9}, {%0,%1,%2,%3};"
                        : "+f"(d[0]), "+f"(d[1]), "+f"(d[2]), "+f"(d[3])
                        : "r"(al[0]), "r"(al[1]), "r"(al[2]), "r"(al[3]),
                          "r"(bh[nf][0]), "r"(bh[nf][1]));
                }
            }
        }
        __syncthreads();
    }

    const int g = lane >> 2;
    const int t = lane & 3;
    #pragma unroll
    for (int mf = 0; mf < 4; ++mf) {
        const int row = bm + wm * 64 + mf * 16 + g;
        #pragma unroll
        for (int nf = 0; nf < 4; ++nf) {
            const int col = bn + wn * 32 + nf * 8 + 2 * t;
            const float b0 = __ldg(bias + col);
            const float b1 = __ldg(bias + col + 1);
            float* d = acc[mf][nf];
            *reinterpret_cast<float2*>(C + (size_t)row * CC + col) =
                make_float2(d[0] + b0, d[1] + b1);
            *reinterpret_cast<float2*>(C + (size_t)(row + 8) * CC + col) =
                make_float2(d[2] + b0, d[3] + b1);
        }
    }
}

// ---------------- gather attention: one WARP per (b,q), all 8 heads ---------
// lane l owns dims {i*128 + l*4 .. +3} for i=0..3; head(i,l) = 2i + (l>>4).
// Contiguous float4 gathers; 16-shfl half-warp reductions give all 8 head dots.
// Writes bf16 hi/lo directly (feeds O-GEMM).
__global__ void __launch_bounds__(256) attn_kernel(
    const float* __restrict__ q, const float* __restrict__ k,
    const float* __restrict__ v, const int* __restrict__ indices,
    const float* __restrict__ weights,
    __nv_bfloat16* __restrict__ ohi, __nv_bfloat16* __restrict__ olo)
{
    __shared__ float slog[8 * 8 * 33];           // per-warp [8 heads][33]
    const int wid  = threadIdx.x >> 5;
    const int lane = threadIdx.x & 31;
    const int bq   = blockIdx.x * 8 + wid;
    const int b    = bq >> 12;
    float* sl = slog + wid * (8 * 33);

    const float* kb = k + (size_t)b * NTGT * CC;
    const float* vb = v + (size_t)b * NTGT * CC;
    const int half  = lane >> 4;                 // 0/1

    const int idxl = indices[(size_t)bq * KNN + lane];

    // q fragments: qf[i] = q[bq][i*128 + lane*4 ..]
    const float4* qrow = reinterpret_cast<const float4*>(q + (size_t)bq * CC);
    float4 qf[4];
    #pragma unroll
    for (int i = 0; i < 4; ++i) qf[i] = qrow[i * 32 + lane];

    // ---- QK pass: logits for all 8 heads ----
    #pragma unroll 4
    for (int j = 0; j < KNN; ++j) {
        const int ij = __shfl_sync(0xffffffffu, idxl, j);
        const float4* krow = reinterpret_cast<const float4*>(kb + (size_t)ij * CC);
        float part[4];
        #pragma unroll
        for (int i = 0; i < 4; ++i) {
            const float4 kf = krow[i * 32 + lane];
            part[i] = qf[i].x * kf.x + qf[i].y * kf.y
                    + qf[i].z * kf.z + qf[i].w * kf.w;
        }
        #pragma unroll
        for (int off = 8; off >= 1; off >>= 1) {
            #pragma unroll
            for (int i = 0; i < 4; ++i)
                part[i] += __shfl_xor_sync(0xffffffffu, part[i], off);
        }
        if ((lane & 15) == 0) {
            #pragma unroll
            for (int i = 0; i < 4; ++i)
                sl[(2 * i + half) * 33 + j] = part[i];
        }
    }
    __syncwarp();

    // ---- softmax: lane handles head lane>>2, js (lane&3)+4t ----
    {
        const int h  = lane >> 2;
        const int j0 = lane & 3;
        float vals[8];
        #pragma unroll
        for (int t = 0; t < 8; ++t) {
            const int j = j0 + 4 * t;
            vals[t] = sl[h * 33 + j] * SCALE
                    + weights[(size_t)bq * KNN + j];
        }
        float m = vals[0];
        #pragma unroll
        for (int t = 1; t < 8; ++t) m = fmaxf(m, vals[t]);
        m = fmaxf(m, __shfl_xor_sync(0xffffffffu, m, 1));
        m = fmaxf(m, __shfl_xor_sync(0xffffffffu, m, 2));
        float s = 0.f;
        #pragma unroll
        for (int t = 0; t < 8; ++t) { vals[t] = __expf(vals[t] - m); s += vals[t]; }
        s += __shfl_xor_sync(0xffffffffu, s, 1);
        s += __shfl_xor_sync(0xffffffffu, s, 2);
        const float inv = 1.f / s;
        #pragma unroll
        for (int t = 0; t < 8; ++t) sl[h * 33 + j0 + 4 * t] = vals[t] * inv;
    }
    __syncwarp();

    // ---- V pass ----
    float4 acc[4];
    #pragma unroll
    for (int i = 0; i < 4; ++i) acc[i] = make_float4(0.f, 0.f, 0.f, 0.f);

    #pragma unroll 4
    for (int j = 0; j < KNN; ++j) {
        const int ij = __shfl_sync(0xffffffffu, idxl, j);
        const float4* vrow = reinterpret_cast<const float4*>(vb + (size_t)ij * CC);
        #pragma unroll
        for (int i = 0; i < 4; ++i) {
            const float pj = sl[(2 * i + half) * 33 + j];
            const float4 vf = vrow[i * 32 + lane];
            acc[i].x = fmaf(pj, vf.x, acc[i].x);
            acc[i].y = fmaf(pj, vf.y, acc[i].y);
            acc[i].z = fmaf(pj, vf.z, acc[i].z);
            acc[i].w = fmaf(pj, vf.w, acc[i].w);
        }
    }

    // ---- epilogue: write bf16 hi/lo splits ----
    #pragma unroll
    for (int i = 0; i < 4; ++i) {
        const size_t d = (size_t)bq * CC + i * 128 + lane * 4;
        __nv_bfloat16 h0 = __float2bfloat16_rn(acc[i].x);
        __nv_bfloat16 h1 = __float2bfloat16_rn(acc[i].y);
        __nv_bfloat16 h2 = __float2bfloat16_rn(acc[i].z);
        __nv_bfloat16 h3 = __float2bfloat16_rn(acc[i].w);
        __nv_bfloat16 l0 = __float2bfloat16_rn(acc[i].x - __bfloat162float(h0));
        __nv_bfloat16 l1 = __float2bfloat16_rn(acc[i].y - __bfloat162float(h1));
        __nv_bfloat16 l2 = __float2bfloat16_rn(acc[i].z - __bfloat162float(h2));
        __nv_bfloat16 l3 = __float2bfloat16_rn(acc[i].w - __bfloat162float(h3));
        *reinterpret_cast<uint2*>(ohi + d) = make_uint2(pack2(h0, h1), pack2(h2, h3));
        *reinterpret_cast<uint2*>(olo + d) = make_uint2(pack2(l0, l1), pack2(l2, l3));
    }
}

// ---------------- launch ----------------------------------------------------
extern "C" void kernel_launch(void* const* d_in, const int* in_sizes, int n_in,
                              void* d_out, int out_size)
{
    const float* src = (const float*)d_in[0];
    const float* tgt = (const float*)d_in[1];
    const int*   idx = (const int*)d_in[2];
    const float* wts = (const float*)d_in[3];
    const float* Wq  = (const float*)d_in[4];
    const float* bq  = (const float*)d_in[5];
    const float* Wk  = (const float*)d_in[6];
    const float* bk  = (const float*)d_in[7];
    const float* Wv  = (const float*)d_in[8];
    const float* bv  = (const float*)d_in[9];
    const float* Wo  = (const float*)d_in[10];
    const float* bo  = (const float*)d_in[11];
    float*       out = (float*)d_out;

    void *pq, *pk, *pv, *pshi, *pslo, *pthi, *ptlo, *pohi, *polo, *pwhi, *pwlo;
    cudaGetSymbolAddress(&pq, g_q);
    cudaGetSymbolAddress(&pk, g_k);
    cudaGetSymbolAddress(&pv, g_v);
    cudaGetSymbolAddress(&pshi, g_Shi);
    cudaGetSymbolAddress(&pslo, g_Slo);
    cudaGetSymbolAddress(&pthi, g_Thi);
    cudaGetSymbolAddress(&ptlo, g_Tlo);
    cudaGetSymbolAddress(&pohi, g_Ohi);
    cudaGetSymbolAddress(&polo, g_Olo);
    cudaGetSymbolAddress(&pwhi, g_Wt_hi);
    cudaGetSymbolAddress(&pwlo, g_Wt_lo);
    float* gq = (float*)pq;
    float* gk = (float*)pk;
    float* gv = (float*)pv;
    __nv_bfloat16* shi = (__nv_bfloat16*)pshi;
    __nv_bfloat16* slo = (__nv_bfloat16*)pslo;
    __nv_bfloat16* thi = (__nv_bfloat16*)pthi;
    __nv_bfloat16* tlo = (__nv_bfloat16*)ptlo;
    __nv_bfloat16* ohi = (__nv_bfloat16*)pohi;
    __nv_bfloat16* olo = (__nv_bfloat16*)polo;
    __nv_bfloat16* whi = (__nv_bfloat16*)pwhi;
    __nv_bfloat16* wlo = (__nv_bfloat16*)pwlo;

    static bool attr_set = false;
    if (!attr_set) {
        cudaFuncSetAttribute(mma_gemm_bias,
                             cudaFuncAttributeMaxDynamicSharedMemorySize, SM_TOT);
        attr_set = true;
    }

    const size_t WS = (size_t)CC * CC;

    // 1. all weight transposes+splits in one launch
    dim3 tgrid(CC / 32, CC / 32, 4), tblk(32, 8);
    transpose_split_all<<<tgrid, tblk>>>(Wq, Wk, Wv, Wo, whi, wlo);

    // 2. src + tgt splits in one launch
    const int nsplit = MROWS * CC / 4 / 256;   // 4096 per tensor
    split2_kernel<<<2 * nsplit, 256>>>(src, tgt, shi, slo, thi, tlo);

    // 3. Q, K, V projections
    dim3 ggrid(CC / 128, MROWS / 128);         // (4, 64)
    mma_gemm_bias<<<ggrid, 256, SM_TOT>>>(shi, slo, whi + 0 * WS, wlo + 0 * WS, bq, gq);
    mma_gemm_bias<<<ggrid, 256, SM_TOT>>>(thi, tlo, whi + 1 * WS, wlo + 1 * WS, bk, gk);
    mma_gemm_bias<<<ggrid, 256, SM_TOT>>>(thi, tlo, whi + 2 * WS, wlo + 2 * WS, bv, gv);

    // 4. attention (writes bf16 hi/lo directly)
    attn_kernel<<<BB * HW / 8, 256>>>(gq, gk, gv, idx, wts, ohi, olo);

    // 5. output projection
    mma_gemm_bias<<<ggrid, 256, SM_TOT>>>(ohi, olo, whi + 3 * WS, wlo + 3 * WS, bo, out);
}

// round 7
// speedup vs baseline: 2.3338x; 1.1079x over previous
#include <cuda_runtime.h>
#include <cuda_bf16.h>
#include <cuda_fp16.h>
#include <cstdint>

// Problem constants
#define BB    2
#define HW    4096
#define NTGT  4096
#define CC    512
#define HH    8
#define KNN   32
#define DH    64
#define MROWS (BB * HW)      // 8192
#define SCALE 0.125f

// ---------------- scratch (device globals: allocation-free) ----------------
__device__ float  g_q[(size_t)MROWS * CC];
__device__ __half g_kh[(size_t)MROWS * CC];
__device__ __half g_vh[(size_t)MROWS * CC];
__device__ __nv_bfloat16 g_Shi[(size_t)MROWS * CC];
__device__ __nv_bfloat16 g_Slo[(size_t)MROWS * CC];
__device__ __nv_bfloat16 g_Thi[(size_t)MROWS * CC];
__device__ __nv_bfloat16 g_Tlo[(size_t)MROWS * CC];
__device__ __nv_bfloat16 g_Ohi[(size_t)MROWS * CC];
__device__ __nv_bfloat16 g_Olo[(size_t)MROWS * CC];
__device__ __nv_bfloat16 g_Wt_hi[4][CC * CC];        // [N][K]
__device__ __nv_bfloat16 g_Wt_lo[4][CC * CC];

// ---------------- helpers ----------------------------------------------------
__device__ __forceinline__ uint32_t smem_to_u32(const void* p) {
    uint32_t a;
    asm("{ .reg .u64 t; cvta.to.shared.u64 t, %1; cvt.u32.u64 %0, t; }"
        : "=r"(a) : "l"(p));
    return a;
}
__device__ __forceinline__ void cp16(uint32_t dst, const void* src) {
    asm volatile("cp.async.cg.shared.global [%0], [%1], 16;" :: "r"(dst), "l"(src));
}
#define CP_COMMIT() asm volatile("cp.async.commit_group;" ::: "memory")
#define CP_WAIT(n)  asm volatile("cp.async.wait_group %0;" :: "n"(n) : "memory")

__device__ __forceinline__ uint32_t pack2(__nv_bfloat16 a, __nv_bfloat16 b) {
    __nv_bfloat162 t; t.x = a; t.y = b;
    return *reinterpret_cast<uint32_t*>(&t);
}

// ---------------- fused weight transpose + split (all 4 weights) ------------
__global__ void transpose_split_all(const float* __restrict__ W0,
                                    const float* __restrict__ W1,
                                    const float* __restrict__ W2,
                                    const float* __restrict__ W3,
                                    __nv_bfloat16* __restrict__ hi,
                                    __nv_bfloat16* __restrict__ lo)
{
    __shared__ float t[32][33];
    const int w  = blockIdx.z;
    const float* W = (w == 0) ? W0 : (w == 1) ? W1 : (w == 2) ? W2 : W3;
    const size_t wo = (size_t)w * CC * CC;
    const int kt = blockIdx.x * 32;
    const int nt = blockIdx.y * 32;
    const int tx = threadIdx.x, ty = threadIdx.y;
    #pragma unroll
    for (int i = 0; i < 4; ++i)
        t[ty + i * 8][tx] = W[(size_t)(kt + ty + i * 8) * CC + nt + tx];
    __syncthreads();
    #pragma unroll
    for (int i = 0; i < 4; ++i) {
        float x = t[tx][ty + i * 8];
        __nv_bfloat16 h = __float2bfloat16_rn(x);
        __nv_bfloat16 l = __float2bfloat16_rn(x - __bfloat162float(h));
        size_t o = wo + (size_t)(nt + ty + i * 8) * CC + kt + tx;
        hi[o] = h;
        lo[o] = l;
    }
}

// ---------------- fused activation split: src + tgt -------------------------
__global__ void __launch_bounds__(256) split2_kernel(
    const float* __restrict__ S, const float* __restrict__ T,
    __nv_bfloat16* __restrict__ shi, __nv_bfloat16* __restrict__ slo,
    __nv_bfloat16* __restrict__ thi, __nv_bfloat16* __restrict__ tlo)
{
    const int half = gridDim.x >> 1;
    const bool is_t = blockIdx.x >= half;
    const float* X = is_t ? T : S;
    __nv_bfloat16* hi = is_t ? thi : shi;
    __nv_bfloat16* lo = is_t ? tlo : slo;
    const int i = (is_t ? blockIdx.x - half : blockIdx.x) * 256 + threadIdx.x;
    const float4 x = reinterpret_cast<const float4*>(X)[i];
    __nv_bfloat16 h0 = __float2bfloat16_rn(x.x);
    __nv_bfloat16 h1 = __float2bfloat16_rn(x.y);
    __nv_bfloat16 h2 = __float2bfloat16_rn(x.z);
    __nv_bfloat16 h3 = __float2bfloat16_rn(x.w);
    __nv_bfloat16 l0 = __float2bfloat16_rn(x.x - __bfloat162float(h0));
    __nv_bfloat16 l1 = __float2bfloat16_rn(x.y - __bfloat162float(h1));
    __nv_bfloat16 l2 = __float2bfloat16_rn(x.z - __bfloat162float(h2));
    __nv_bfloat16 l3 = __float2bfloat16_rn(x.w - __bfloat162float(h3));
    reinterpret_cast<uint2*>(hi)[i] = make_uint2(pack2(h0, h1), pack2(h2, h3));
    reinterpret_cast<uint2*>(lo)[i] = make_uint2(pack2(l0, l1), pack2(l2, l3));
}

// ---------------- bf16 mma.sync GEMM v2: 128x256 tile, 3-stage, 512 thr -----
// C[M,N] = A@Wt^T + bias; 3-term bf16 split; OutT = float or __half.
#define ROWB 80
#define A_STG (128 * ROWB)          // 10240
#define B_STG (256 * ROWB)          // 20480
#define OFF_AHI 0
#define OFF_ALO (3 * A_STG)         // 30720
#define OFF_BHI (6 * A_STG)         // 61440
#define OFF_BLO (OFF_BHI + 3 * B_STG)
#define SM_TOT  (OFF_BLO + 3 * B_STG)   // 184320

template <typename OutT>
__device__ __forceinline__ void store2(OutT* p, float a, float b);
template <> __device__ __forceinline__ void store2<float>(float* p, float a, float b) {
    *reinterpret_cast<float2*>(p) = make_float2(a, b);
}
template <> __device__ __forceinline__ void store2<__half>(__half* p, float a, float b) {
    *reinterpret_cast<__half2*>(p) = __floats2half2_rn(a, b);
}

template <typename OutT>
__global__ void __launch_bounds__(512, 1) mma_gemm_bias(
    const __nv_bfloat16* __restrict__ Ahi, const __nv_bfloat16* __restrict__ Alo,
    const __nv_bfloat16* __restrict__ Whi, const __nv_bfloat16* __restrict__ Wlo,
    const float* __restrict__ bias, OutT* __restrict__ C)
{
    extern __shared__ char sm[];
    const uint32_t sb = smem_to_u32(sm);
    const int tid  = threadIdx.x;
    const int wid  = tid >> 5;
    const int lane = tid & 31;
    const int bm   = blockIdx.y * 128;
    const int bn   = blockIdx.x * 256;
    const int wm   = wid & 1;          // 0..1  (m 64-half)
    const int wn   = wid >> 1;         // 0..7  (n 32-slice)

    const int ar = tid >> 2;           // 0..127
    const int aq = tid & 3;            // 16B chunk

    float acc[4][4][4];
    #pragma unroll
    for (int a = 0; a < 4; ++a)
        #pragma unroll
        for (int b = 0; b < 4; ++b)
            #pragma unroll
            for (int c = 0; c < 4; ++c) acc[a][b][c] = 0.f;

    auto load_stage = [&](int s, int kt) {
        const int kb = kt * 32;
        {
            const uint32_t so = (uint32_t)(ar * ROWB + aq * 16 + s * A_STG);
            const size_t  ga = (size_t)(bm + ar) * CC + kb + aq * 8;
            cp16(sb + OFF_AHI + so, Ahi + ga);
            cp16(sb + OFF_ALO + so, Alo + ga);
        }
        #pragma unroll
        for (int c = 0; c < 2; ++c) {
            const int row = c * 128 + ar;
            const uint32_t so = (uint32_t)(row * ROWB + aq * 16 + s * B_STG);
            const size_t  gb = (size_t)(bn + row) * CC + kb + aq * 8;
            cp16(sb + OFF_BHI + so, Whi + gb);
            cp16(sb + OFF_BLO + so, Wlo + gb);
        }
    };

    load_stage(0, 0);
    CP_COMMIT();
    load_stage(1, 1);
    CP_COMMIT();

    const int sub16 = lane & 15;
    const int ahalf = lane >> 4;
    const int bn8   = lane & 7;
    const int bk16  = (lane >> 3) & 1;

    #pragma unroll 1
    for (int kt = 0; kt < 16; ++kt) {
        const int s = kt % 3;
        if (kt >= 14) { CP_WAIT(0); } else { CP_WAIT(1); }
        __syncthreads();
        if (kt + 2 < 16) {
            load_stage((kt + 2) % 3, kt + 2);
            CP_COMMIT();
        }

        const uint32_t aBase = sb + (uint32_t)(s * A_STG);
        const uint32_t bBase = sb + (uint32_t)(s * B_STG);

        #pragma unroll
        for (int s2 = 0; s2 < 2; ++s2) {
            const int kbyte = s2 * 32;
            uint32_t bh[4][2], bl[4][2];
            #pragma unroll
            for (int nf = 0; nf < 4; ++nf) {
                const uint32_t brow = (uint32_t)(wn * 32 + nf * 8 + bn8);
                const uint32_t ba = bBase + brow * ROWB + kbyte + bk16 * 16;
                asm volatile(
                    "ldmatrix.sync.aligned.m8n8.x2.shared.b16 {%0,%1}, [%2];"
                    : "=r"(bh[nf][0]), "=r"(bh[nf][1]) : "r"(ba + OFF_BHI));
                asm volatile(
                    "ldmatrix.sync.aligned.m8n8.x2.shared.b16 {%0,%1}, [%2];"
                    : "=r"(bl[nf][0]), "=r"(bl[nf][1]) : "r"(ba + OFF_BLO));
            }
            #pragma unroll
            for (int mf = 0; mf < 4; ++mf) {
                const uint32_t arow = (uint32_t)(wm * 64 + mf * 16 + sub16);
                const uint32_t aa = aBase + arow * ROWB + kbyte + ahalf * 16;
                uint32_t ah[4], al[4];
                asm volatile(
                    "ldmatrix.sync.aligned.m8n8.x4.shared.b16 {%0,%1,%2,%3}, [%4];"
                    : "=r"(ah[0]), "=r"(ah[1]), "=r"(ah[2]), "=r"(ah[3])
                    : "r"(aa + OFF_AHI));
                asm volatile(
                    "ldmatrix.sync.aligned.m8n8.x4.shared.b16 {%0,%1,%2,%3}, [%4];"
                    : "=r"(al[0]), "=r"(al[1]), "=r"(al[2]), "=r"(al[3])
                    : "r"(aa + OFF_ALO));
                #pragma unroll
                for (int nf = 0; nf < 4; ++nf) {
                    float* d = acc[mf][nf];
                    asm volatile(
                        "mma.sync.aligned.m16n8k16.row.col.f32.bf16.bf16.f32 "
                        "{%0,%1,%2,%3}, {%4,%5,%6,%7}, {%8,%9}, {%0,%1,%2,%3};"
                        : "+f"(d[0]), "+f"(d[1]), "+f"(d[2]), "+f"(d[3])
                        : "r"(ah[0]), "r"(ah[1]), "r"(ah[2]), "r"(ah[3]),
                          "r"(bh[nf][0]), "r"(bh[nf][1]));
                    asm volatile(
                        "mma.sync.aligned.m16n8k16.row.col.f32.bf16.bf16.f32 "
                        "{%0,%1,%2,%3}, {%4,%5,%6,%7}, {%8,%9}, {%0,%1,%2,%3};"
                        : "+f"(d[0]), "+f"(d[1]), "+f"(d[2]), "+f"(d[3])
                        : "r"(ah[0]), "r"(ah[1]), "r"(ah[2]), "r"(ah[3]),
                          "r"(bl[nf][0]), "r"(bl[nf][1]));
                    asm volatile(
                        "mma.sync.aligned.m16n8k16.row.col.f32.bf16.bf16.f32 "
                        "{%0,%1,%2,%3}, {%4,%5,%6,%7}, {%8,%9}, {%0,%1,%2,%3};"
                        : "+f"(d[0]), "+f"(d[1]), "+f"(d[2]), "+f"(d[3])
                        : "r"(al[0]), "r"(al[1]), "r"(al[2]), "r"(al[3]),
                          "r"(bh[nf][0]), "r"(bh[nf][1]));
                }
            }
        }
    }

    const int g = lane >> 2;
    const int t = lane & 3;
    #pragma unroll
    for (int mf = 0; mf < 4; ++mf) {
        const int row = bm + wm * 64 + mf * 16 + g;
        #pragma unroll
        for (int nf = 0; nf < 4; ++nf) {
            const int col = bn + wn * 32 + nf * 8 + 2 * t;
            const float b0 = __ldg(bias + col);
            const float b1 = __ldg(bias + col + 1);
            float* d = acc[mf][nf];
            store2<OutT>(C + (size_t)row * CC + col, d[0] + b0, d[1] + b1);
            store2<OutT>(C + (size_t)(row + 8) * CC + col, d[2] + b0, d[3] + b1);
        }
    }
}

// ---------------- gather attention: fp16 K/V, one warp per (b,q) ------------
// lane l owns dims {i*256 + l*8 .. +7}, i=0..1; head = i*4 + (l>>3).
__global__ void __launch_bounds__(256) attn_kernel(
    const float* __restrict__ q, const __half* __restrict__ k,
    const __half* __restrict__ v, const int* __restrict__ indices,
    const float* __restrict__ weights,
    __nv_bfloat16* __restrict__ ohi, __nv_bfloat16* __restrict__ olo)
{
    __shared__ float slog[8 * 8 * 33];
    const int wid  = threadIdx.x >> 5;
    const int lane = threadIdx.x & 31;
    const int bq   = blockIdx.x * 8 + wid;
    const int b    = bq >> 12;
    float* sl = slog + wid * (8 * 33);

    const __half* kb = k + (size_t)b * NTGT * CC;
    const __half* vb = v + (size_t)b * NTGT * CC;

    const int idxl = indices[(size_t)bq * KNN + lane];

    // q fragments: 2 x 8 floats
    float qf[2][8];
    {
        const float4* qrow = reinterpret_cast<const float4*>(q + (size_t)bq * CC);
        #pragma unroll
        for (int i = 0; i < 2; ++i) {
            float4 a = qrow[i * 64 + lane * 2];
            float4 c = qrow[i * 64 + lane * 2 + 1];
            qf[i][0] = a.x; qf[i][1] = a.y; qf[i][2] = a.z; qf[i][3] = a.w;
            qf[i][4] = c.x; qf[i][5] = c.y; qf[i][6] = c.z; qf[i][7] = c.w;
        }
    }

    // ---- QK pass ----
    #pragma unroll 4
    for (int j = 0; j < KNN; ++j) {
        const int ij = __shfl_sync(0xffffffffu, idxl, j);
        const uint4* krow = reinterpret_cast<const uint4*>(kb + (size_t)ij * CC);
        float part[2];
        #pragma unroll
        for (int i = 0; i < 2; ++i) {
            const uint4 kk = krow[i * 32 + lane];
            const __half2* kh = reinterpret_cast<const __half2*>(&kk);
            float p = 0.f;
            #pragma unroll
            for (int h2 = 0; h2 < 4; ++h2) {
                const float2 kf = __half22float2(kh[h2]);
                p = fmaf(qf[i][2 * h2], kf.x, p);
                p = fmaf(qf[i][2 * h2 + 1], kf.y, p);
            }
            part[i] = p;
        }
        #pragma unroll
        for (int off = 4; off >= 1; off >>= 1) {
            part[0] += __shfl_xor_sync(0xffffffffu, part[0], off);
            part[1] += __shfl_xor_sync(0xffffffffu, part[1], off);
        }
        if ((lane & 7) == 0) {
            sl[(0 * 4 + (lane >> 3)) * 33 + j] = part[0];
            sl[(1 * 4 + (lane >> 3)) * 33 + j] = part[1];
        }
    }
    __syncwarp();

    // ---- softmax: lane -> head lane>>2, js (lane&3)+4t ----
    {
        const int h  = lane >> 2;
        const int j0 = lane & 3;
        float vals[8];
        #pragma unroll
        for (int t = 0; t < 8; ++t) {
            const int j = j0 + 4 * t;
            vals[t] = sl[h * 33 + j] * SCALE + weights[(size_t)bq * KNN + j];
        }
        float m = vals[0];
        #pragma unroll
        for (int t = 1; t < 8; ++t) m = fmaxf(m, vals[t]);
        m = fmaxf(m, __shfl_xor_sync(0xffffffffu, m, 1));
        m = fmaxf(m, __shfl_xor_sync(0xffffffffu, m, 2));
        float s = 0.f;
        #pragma unroll
        for (int t = 0; t < 8; ++t) { vals[t] = __expf(vals[t] - m); s += vals[t]; }
        s += __shfl_xor_sync(0xffffffffu, s, 1);
        s += __shfl_xor_sync(0xffffffffu, s, 2);
        const float inv = 1.f / s;
        #pragma unroll
        for (int t = 0; t < 8; ++t) sl[h * 33 + j0 + 4 * t] = vals[t] * inv;
    }
    __syncwarp();

    // ---- V pass ----
    float acc[2][8];
    #pragma unroll
    for (int i = 0; i < 2; ++i)
        #pragma unroll
        for (int d = 0; d < 8; ++d) acc[i][d] = 0.f;

    const int hsub = lane >> 3;
    #pragma unroll 4
    for (int j = 0; j < KNN; ++j) {
        const int ij = __shfl_sync(0xffffffffu, idxl, j);
        const uint4* vrow = reinterpret_cast<const uint4*>(vb + (size_t)ij * CC);
        #pragma unroll
        for (int i = 0; i < 2; ++i) {
            const float pj = sl[(i * 4 + hsub) * 33 + j];
            const uint4 vv = vrow[i * 32 + lane];
            const __half2* vh = reinterpret_cast<const __half2*>(&vv);
            #pragma unroll
            for (int h2 = 0; h2 < 4; ++h2) {
                const float2 vf = __half22float2(vh[h2]);
                acc[i][2 * h2]     = fmaf(pj, vf.x, acc[i][2 * h2]);
                acc[i][2 * h2 + 1] = fmaf(pj, vf.y, acc[i][2 * h2 + 1]);
            }
        }
    }

    // ---- epilogue: bf16 hi/lo ----
    #pragma unroll
    for (int i = 0; i < 2; ++i) {
        const size_t d = (size_t)bq * CC + i * 256 + lane * 8;
        uint32_t hw[4], lw[4];
        #pragma unroll
        for (int p = 0; p < 4; ++p) {
            float x0 = acc[i][2 * p], x1 = acc[i][2 * p + 1];
            __nv_bfloat16 h0 = __float2bfloat16_rn(x0);
            __nv_bfloat16 h1 = __float2bfloat16_rn(x1);
            __nv_bfloat16 l0 = __float2bfloat16_rn(x0 - __bfloat162float(h0));
            __nv_bfloat16 l1 = __float2bfloat16_rn(x1 - __bfloat162float(h1));
            hw[p] = pack2(h0, h1);
            lw[p] = pack2(l0, l1);
        }
        *reinterpret_cast<uint4*>(ohi + d) = make_uint4(hw[0], hw[1], hw[2], hw[3]);
        *reinterpret_cast<uint4*>(olo + d) = make_uint4(lw[0], lw[1], lw[2], lw[3]);
    }
}

// ---------------- launch ----------------------------------------------------
extern "C" void kernel_launch(void* const* d_in, const int* in_sizes, int n_in,
                              void* d_out, int out_size)
{
    const float* src = (const float*)d_in[0];
    const float* tgt = (const float*)d_in[1];
    const int*   idx = (const int*)d_in[2];
    const float* wts = (const float*)d_in[3];
    const float* Wq  = (const float*)d_in[4];
    const float* bq  = (const float*)d_in[5];
    const float* Wk  = (const float*)d_in[6];
    const float* bk  = (const float*)d_in[7];
    const float* Wv  = (const float*)d_in[8];
    const float* bv  = (const float*)d_in[9];
    const float* Wo  = (const float*)d_in[10];
    const float* bo  = (const float*)d_in[11];
    float*       out = (float*)d_out;

    void *pq, *pkh, *pvh, *pshi, *pslo, *pthi, *ptlo, *pohi, *polo, *pwhi, *pwlo;
    cudaGetSymbolAddress(&pq, g_q);
    cudaGetSymbolAddress(&pkh, g_kh);
    cudaGetSymbolAddress(&pvh, g_vh);
    cudaGetSymbolAddress(&pshi, g_Shi);
    cudaGetSymbolAddress(&pslo, g_Slo);
    cudaGetSymbolAddress(&pthi, g_Thi);
    cudaGetSymbolAddress(&ptlo, g_Tlo);
    cudaGetSymbolAddress(&pohi, g_Ohi);
    cudaGetSymbolAddress(&polo, g_Olo);
    cudaGetSymbolAddress(&pwhi, g_Wt_hi);
    cudaGetSymbolAddress(&pwlo, g_Wt_lo);
    float*  gq  = (float*)pq;
    __half* gkh = (__half*)pkh;
    __half* gvh = (__half*)pvh;
    __nv_bfloat16* shi = (__nv_bfloat16*)pshi;
    __nv_bfloat16* slo = (__nv_bfloat16*)pslo;
    __nv_bfloat16* thi = (__nv_bfloat16*)pthi;
    __nv_bfloat16* tlo = (__nv_bfloat16*)ptlo;
    __nv_bfloat16* ohi = (__nv_bfloat16*)pohi;
    __nv_bfloat16* olo = (__nv_bfloat16*)polo;
    __nv_bfloat16* whi = (__nv_bfloat16*)pwhi;
    __nv_bfloat16* wlo = (__nv_bfloat16*)pwlo;

    static bool attr_set = false;
    if (!attr_set) {
        cudaFuncSetAttribute(mma_gemm_bias<float>,
                             cudaFuncAttributeMaxDynamicSharedMemorySize, SM_TOT);
        cudaFuncSetAttribute(mma_gemm_bias<__half>,
                             cudaFuncAttributeMaxDynamicSharedMemorySize, SM_TOT);
        attr_set = true;
    }

    const size_t WS = (size_t)CC * CC;

    dim3 tgrid(CC / 32, CC / 32, 4), tblk(32, 8);
    transpose_split_all<<<tgrid, tblk>>>(Wq, Wk, Wv, Wo, whi, wlo);

    const int nsplit = MROWS * CC / 4 / 256;
    split2_kernel<<<2 * nsplit, 256>>>(src, tgt, shi, slo, thi, tlo);

    dim3 ggrid(CC / 256, MROWS / 128);   // (2, 64) = 128 CTAs
    mma_gemm_bias<float><<<ggrid, 512, SM_TOT>>>(shi, slo, whi + 0 * WS, wlo + 0 * WS, bq, gq);
    mma_gemm_bias<__half><<<ggrid, 512, SM_TOT>>>(thi, tlo, whi + 1 * WS, wlo + 1 * WS, bk, gkh);
    mma_gemm_bias<__half><<<ggrid, 512, SM_TOT>>>(thi, tlo, whi + 2 * WS, wlo + 2 * WS, bv, gvh);

    attn_kernel<<<BB * HW / 8, 256>>>(gq, gkh, gvh, idx, wts, ohi, olo);

    mma_gemm_bias<float><<<ggrid, 512, SM_TOT>>>(ohi, olo, whi + 3 * WS, wlo + 3 * WS, bo, out);
}